// round 2
// baseline (speedup 1.0000x reference)
#include <cuda_runtime.h>
#include <math.h>

// Problem constants
constexpr int cB  = 2;
constexpr int cS  = 2048;
constexpr int cD  = 1024;
constexpr int cH  = 16;
constexpr int cHD = 64;
constexpr int cM  = cB * cS;  // 4096 rows

// Scratch (allocation-free rule: __device__ globals)
__device__ float g_Q[cM * cD];
__device__ float g_K[cM * cD];
__device__ float g_V[cM * cD];
__device__ float g_ctx[cM * cD];

// ---------------------------------------------------------------------------
// SGEMM: C[M,N] = A[M,K] @ B[K,N] (+ bias[N])
// 128x128 block tile, BK=16, 256 threads, 8x8 per thread.
// ---------------------------------------------------------------------------
constexpr int BM = 128, BN = 128, BK = 16, TM = 8, TN = 8;

__global__ void __launch_bounds__(256) sgemm_kernel(
    const float* __restrict__ A, const float* __restrict__ Bm,
    const float* __restrict__ bias, float* __restrict__ C,
    int Md, int Nd, int Kd)
{
    __shared__ float As[BK][BM];
    __shared__ float Bs[BK][BN];

    const int tid = threadIdx.x;
    const int tx = tid & 15;        // 0..15  (N direction)
    const int ty = tid >> 4;        // 0..15  (M direction)
    const int m0 = blockIdx.y * BM;
    const int n0 = blockIdx.x * BN;

    // A-tile load mapping: 128x16 floats, each thread 2 x float4
    const int ar = tid >> 2;         // 0..63
    const int ac = (tid & 3) << 2;   // 0,4,8,12
    // B-tile load mapping: 16x128 floats, each thread 2 x float4
    const int br = tid >> 5;         // 0..7
    const int bc = (tid & 31) << 2;  // 0..124

    float acc[TM][TN];
#pragma unroll
    for (int i = 0; i < TM; i++)
#pragma unroll
        for (int j = 0; j < TN; j++) acc[i][j] = 0.f;

    const float* Ap = A + (size_t)m0 * Kd;
    const float* Bp = Bm + n0;

    for (int k0 = 0; k0 < Kd; k0 += BK) {
        float4 a0 = *(const float4*)(Ap + (size_t)ar * Kd + k0 + ac);
        float4 a1 = *(const float4*)(Ap + (size_t)(ar + 64) * Kd + k0 + ac);
        float4 b0 = *(const float4*)(Bp + (size_t)(k0 + br) * Nd + bc);
        float4 b1 = *(const float4*)(Bp + (size_t)(k0 + br + 8) * Nd + bc);

        As[ac + 0][ar] = a0.x; As[ac + 1][ar] = a0.y;
        As[ac + 2][ar] = a0.z; As[ac + 3][ar] = a0.w;
        As[ac + 0][ar + 64] = a1.x; As[ac + 1][ar + 64] = a1.y;
        As[ac + 2][ar + 64] = a1.z; As[ac + 3][ar + 64] = a1.w;
        *(float4*)&Bs[br][bc]     = b0;
        *(float4*)&Bs[br + 8][bc] = b1;
        __syncthreads();

#pragma unroll
        for (int k = 0; k < BK; k++) {
            float a[TM], b[TN];
#pragma unroll
            for (int i = 0; i < TM; i += 4)
                *(float4*)&a[i] = *(const float4*)&As[k][ty * TM + i];
#pragma unroll
            for (int j = 0; j < TN; j += 4)
                *(float4*)&b[j] = *(const float4*)&Bs[k][tx * TN + j];
#pragma unroll
            for (int i = 0; i < TM; i++)
#pragma unroll
                for (int j = 0; j < TN; j++)
                    acc[i][j] = fmaf(a[i], b[j], acc[i][j]);
        }
        __syncthreads();
    }

    float bv[TN];
    if (bias) {
#pragma unroll
        for (int j = 0; j < TN; j++) bv[j] = bias[n0 + tx * TN + j];
    } else {
#pragma unroll
        for (int j = 0; j < TN; j++) bv[j] = 0.f;
    }

#pragma unroll
    for (int i = 0; i < TM; i++) {
        float* cp = C + (size_t)(m0 + ty * TM + i) * Nd + n0 + tx * TN;
        float4 o0 = make_float4(acc[i][0] + bv[0], acc[i][1] + bv[1],
                                acc[i][2] + bv[2], acc[i][3] + bv[3]);
        float4 o1 = make_float4(acc[i][4] + bv[4], acc[i][5] + bv[5],
                                acc[i][6] + bv[6], acc[i][7] + bv[7]);
        *(float4*)cp       = o0;
        *(float4*)(cp + 4) = o1;
    }
}

// ---------------------------------------------------------------------------
// Causal flash attention, fp32. One CTA per (q-tile of 128 rows, head, batch);
// one thread per q row. K/V streamed through 32x64 shared tiles.
// Writes ctx as [b, s, h, hd] (== [M, D] for the out projection).
// ---------------------------------------------------------------------------
__global__ void __launch_bounds__(128) attn_kernel(
    const float* __restrict__ Q, const float* __restrict__ K,
    const float* __restrict__ V, float* __restrict__ ctx)
{
    constexpr int Br = 128, Bc = 32;
    const int qt = blockIdx.x;
    const int h  = blockIdx.y;
    const int b  = blockIdx.z;
    const int row = qt * Br + threadIdx.x;   // global q index in sequence

    const float* qp = Q + ((size_t)(b * cS + row) * cD + h * cHD);
    float q[cHD];
#pragma unroll
    for (int d = 0; d < cHD; d += 4) {
        float4 t = *(const float4*)(qp + d);
        q[d]     = t.x * 0.125f;   // 1/sqrt(64)
        q[d + 1] = t.y * 0.125f;
        q[d + 2] = t.z * 0.125f;
        q[d + 3] = t.w * 0.125f;
    }

    float m = -INFINITY, l = 0.f;
    float acc[cHD];
#pragma unroll
    for (int d = 0; d < cHD; d++) acc[d] = 0.f;

    __shared__ float Ks[Bc][cHD];
    __shared__ float Vs[Bc][cHD];

    const int ntiles = qt * 4 + 4;          // tiles up to causal boundary
    const int lr = threadIdx.x >> 2;        // 0..31 (tile row)
    const int lc = (threadIdx.x & 3) << 4;  // 0,16,32,48 (col offset)

    for (int t = 0; t < ntiles; t++) {
        const int k0 = t * Bc;
        const float* kp = K + ((size_t)(b * cS + k0 + lr) * cD + h * cHD + lc);
        const float* vp = V + ((size_t)(b * cS + k0 + lr) * cD + h * cHD + lc);
#pragma unroll
        for (int i = 0; i < 16; i += 4) {
            *(float4*)&Ks[lr][lc + i] = *(const float4*)(kp + i);
            *(float4*)&Vs[lr][lc + i] = *(const float4*)(vp + i);
        }
        __syncthreads();

        float sc[Bc];
        float mt = m;
        const bool full = (k0 + Bc - 1 <= row);  // tile fully unmasked
#pragma unroll 8
        for (int j = 0; j < Bc; j++) {
            float s0 = 0.f, s1 = 0.f;
#pragma unroll
            for (int d = 0; d < cHD; d += 8) {
                float4 ka = *(const float4*)&Ks[j][d];
                float4 kb = *(const float4*)&Ks[j][d + 4];
                s0 = fmaf(q[d],     ka.x, s0);
                s0 = fmaf(q[d + 1], ka.y, s0);
                s0 = fmaf(q[d + 2], ka.z, s0);
                s0 = fmaf(q[d + 3], ka.w, s0);
                s1 = fmaf(q[d + 4], kb.x, s1);
                s1 = fmaf(q[d + 5], kb.y, s1);
                s1 = fmaf(q[d + 6], kb.z, s1);
                s1 = fmaf(q[d + 7], kb.w, s1);
            }
            float s = s0 + s1;
            if (!full && (k0 + j > row)) s = -INFINITY;
            sc[j] = s;
            mt = fmaxf(mt, s);
        }

        const float corr = __expf(m - mt);  // m=-inf, mt finite -> 0 (safe)
        l *= corr;
#pragma unroll
        for (int d = 0; d < cHD; d++) acc[d] *= corr;

#pragma unroll 8
        for (int j = 0; j < Bc; j++) {
            const float p = __expf(sc[j] - mt);
            l += p;
#pragma unroll
            for (int d = 0; d < cHD; d += 4) {
                float4 v4 = *(const float4*)&Vs[j][d];
                acc[d]     = fmaf(p, v4.x, acc[d]);
                acc[d + 1] = fmaf(p, v4.y, acc[d + 1]);
                acc[d + 2] = fmaf(p, v4.z, acc[d + 2]);
                acc[d + 3] = fmaf(p, v4.w, acc[d + 3]);
            }
        }
        m = mt;
        __syncthreads();
    }

    const float inv = 1.f / l;
    float* op = ctx + ((size_t)(b * cS + row) * cD + h * cHD);
#pragma unroll
    for (int d = 0; d < cHD; d += 4) {
        float4 o = make_float4(acc[d] * inv, acc[d + 1] * inv,
                               acc[d + 2] * inv, acc[d + 3] * inv);
        *(float4*)(op + d) = o;
    }
}

// ---------------------------------------------------------------------------
// Launch: QKV projections -> causal flash attention -> output projection
// ---------------------------------------------------------------------------
extern "C" void kernel_launch(void* const* d_in, const int* /*in_sizes*/, int /*n_in*/,
                              void* d_out, int /*out_size*/)
{
    const float* x  = (const float*)d_in[0];
    const float* Wq = (const float*)d_in[1];
    const float* Wk = (const float*)d_in[2];
    const float* Wv = (const float*)d_in[3];
    const float* Wo = (const float*)d_in[4];
    const float* bo = (const float*)d_in[5];
    float* out = (float*)d_out;

    float *Qp, *Kp, *Vp, *Cp;
    cudaGetSymbolAddress((void**)&Qp, g_Q);
    cudaGetSymbolAddress((void**)&Kp, g_K);
    cudaGetSymbolAddress((void**)&Vp, g_V);
    cudaGetSymbolAddress((void**)&Cp, g_ctx);

    dim3 gg(cD / BN, cM / BM);   // (8, 32)
    sgemm_kernel<<<gg, 256>>>(x, Wq, nullptr, Qp, cM, cD, cD);
    sgemm_kernel<<<gg, 256>>>(x, Wk, nullptr, Kp, cM, cD, cD);
    sgemm_kernel<<<gg, 256>>>(x, Wv, nullptr, Vp, cM, cD, cD);

    dim3 ga(cS / 128, cH, cB);   // (16, 16, 2)
    attn_kernel<<<ga, 128>>>(Qp, Kp, Vp, Cp);

    sgemm_kernel<<<gg, 256>>>(Cp, Wo, bo, out, cM, cD, cD);
}

// round 4
// speedup vs baseline: 1.2876x; 1.2876x over previous
#include <cuda_runtime.h>
#include <cuda_bf16.h>
#include <cstdint>
#include <math.h>

// Problem constants
constexpr int cB  = 2;
constexpr int cS  = 2048;
constexpr int cD  = 1024;
constexpr int cH  = 16;
constexpr int cHD = 64;
constexpr int cM  = cB * cS;  // 4096 rows

// ---------------------------------------------------------------------------
// Scratch (allocation-free rule: __device__ globals)
// ---------------------------------------------------------------------------
__device__ float g_Q[cM * cD];
__device__ float g_K[cM * cD];
__device__ float g_V[cM * cD];
__device__ float g_ctx[cM * cD];
__device__ __nv_bfloat16 g_xh[cM * cD];
__device__ __nv_bfloat16 g_xl[cM * cD];
__device__ __nv_bfloat16 g_ch[cM * cD];
__device__ __nv_bfloat16 g_cl[cM * cD];
__device__ __nv_bfloat16 g_Wqh[cD * cD], g_Wql[cD * cD];
__device__ __nv_bfloat16 g_Wkh[cD * cD], g_Wkl[cD * cD];
__device__ __nv_bfloat16 g_Wvh[cD * cD], g_Wvl[cD * cD];
__device__ __nv_bfloat16 g_Woh[cD * cD], g_Wol[cD * cD];

// ---------------------------------------------------------------------------
// Helpers (sm_80-era features only: ldmatrix, mma.sync bf16, cp.async)
// ---------------------------------------------------------------------------
__device__ __forceinline__ uint32_t smem_to_u32(const void* smem_ptr) {
    uint32_t addr;
    asm("{ .reg .u64 tmp; cvta.to.shared.u64 tmp, %1; cvt.u32.u64 %0, tmp; }"
        : "=r"(addr) : "l"(smem_ptr));
    return addr;
}

__device__ __forceinline__ void cp_async16(uint32_t dst, const void* src) {
    asm volatile("cp.async.cg.shared.global [%0], [%1], 16;" :: "r"(dst), "l"(src));
}
#define CP_COMMIT() asm volatile("cp.async.commit_group;" ::: "memory")
#define CP_WAIT0()  asm volatile("cp.async.wait_group 0;"  ::: "memory")

__device__ __forceinline__ void ldmx4(uint32_t* d, uint32_t addr) {
    asm volatile("ldmatrix.sync.aligned.m8n8.x4.shared.b16 {%0,%1,%2,%3}, [%4];"
                 : "=r"(d[0]), "=r"(d[1]), "=r"(d[2]), "=r"(d[3]) : "r"(addr));
}

__device__ __forceinline__ void mma16816(float* c, const uint32_t* a,
                                         uint32_t b0, uint32_t b1) {
    asm volatile(
        "mma.sync.aligned.m16n8k16.row.col.f32.bf16.bf16.f32 "
        "{%0,%1,%2,%3}, {%4,%5,%6,%7}, {%8,%9}, {%0,%1,%2,%3};"
        : "+f"(c[0]), "+f"(c[1]), "+f"(c[2]), "+f"(c[3])
        : "r"(a[0]), "r"(a[1]), "r"(a[2]), "r"(a[3]), "r"(b0), "r"(b1));
}

// ---------------------------------------------------------------------------
// bf16-split (Ootomo) mma.sync GEMM: C[M,N] = (Ah+Al)[M,K] @ (Bh+Bl)[N,K]^T (+bias)
// 128x128x32 tile, 256 threads (8 warps, 4x2), warp tile 32x64,
// cp.async double-buffered, +8 padded smem rows (conflict-free ldmatrix).
// ---------------------------------------------------------------------------
constexpr int BKg = 32;
constexpr int LDT = BKg + 8;                    // 40 bf16 per smem row
constexpr int TILE_E  = 128 * LDT;              // elems per tile (5120)
constexpr int STAGE_E = 4 * TILE_E;             // Ah, Al, Bh, Bl
constexpr int GEMM_SMEM = 2 * STAGE_E * 2;      // bytes (81920)
constexpr int NCH = cD / BKg;                   // 32 k-chunks

__global__ void __launch_bounds__(256) gemm_bf16x3_kernel(
    const __nv_bfloat16* __restrict__ Ah, const __nv_bfloat16* __restrict__ Al,
    const __nv_bfloat16* __restrict__ Bh, const __nv_bfloat16* __restrict__ Bl,
    const float* __restrict__ bias, float* __restrict__ C,
    int Kd, int Nd)
{
    extern __shared__ __nv_bfloat16 sm[];
    const uint32_t sbase = smem_to_u32(sm);

    const int tid  = threadIdx.x;
    const int wid  = tid >> 5;
    const int lane = tid & 31;
    const int m0 = blockIdx.y * 128;
    const int n0 = blockIdx.x * 128;

    // Loader mapping: vector v in [0,512): row=v>>2, 16B seg=v&3; 2 vectors/thread/tile
    const int r0v = tid >> 2, s0v = tid & 3;          // vector tid
    const int r1v = (tid + 256) >> 2, s1v = tid & 3;  // vector tid+256

    const __nv_bfloat16* gAh = Ah + (size_t)m0 * Kd;
    const __nv_bfloat16* gAl = Al + (size_t)m0 * Kd;
    const __nv_bfloat16* gBh = Bh + (size_t)n0 * Kd;
    const __nv_bfloat16* gBl = Bl + (size_t)n0 * Kd;

    auto load_stage = [&](int chunk, int stage) {
        const int k0 = chunk * BKg;
        const uint32_t sb = sbase + (uint32_t)stage * STAGE_E * 2;
        const uint32_t o0 = (uint32_t)(r0v * LDT + s0v * 8) * 2;
        const uint32_t o1 = (uint32_t)(r1v * LDT + s1v * 8) * 2;
        const size_t g0 = (size_t)r0v * Kd + k0 + s0v * 8;
        const size_t g1 = (size_t)r1v * Kd + k0 + s1v * 8;
        cp_async16(sb + o0,                  gAh + g0);
        cp_async16(sb + o1,                  gAh + g1);
        cp_async16(sb + TILE_E * 2 + o0,     gAl + g0);
        cp_async16(sb + TILE_E * 2 + o1,     gAl + g1);
        cp_async16(sb + 2 * TILE_E * 2 + o0, gBh + g0);
        cp_async16(sb + 2 * TILE_E * 2 + o1, gBh + g1);
        cp_async16(sb + 3 * TILE_E * 2 + o0, gBl + g0);
        cp_async16(sb + 3 * TILE_E * 2 + o1, gBl + g1);
    };

    // Warp tiling: 4 (m) x 2 (n) warps; warp tile 32x64
    const int mb = (wid >> 1) * 32;
    const int nb = (wid & 1) * 64;
    const int lr  = lane & 7;       // ldmatrix row within 8
    const int sub = lane >> 3;      // ldmatrix submatrix id

    float acc[2][8][4];
#pragma unroll
    for (int i = 0; i < 2; i++)
#pragma unroll
        for (int j = 0; j < 8; j++)
#pragma unroll
            for (int q = 0; q < 4; q++) acc[i][j][q] = 0.f;

    load_stage(0, 0);
    CP_COMMIT();

    for (int i = 0; i < NCH; i++) {
        CP_WAIT0();
        __syncthreads();
        if (i + 1 < NCH) { load_stage(i + 1, (i + 1) & 1); CP_COMMIT(); }

        const uint32_t sb  = sbase + (uint32_t)(i & 1) * STAGE_E * 2;
        const uint32_t sAh = sb;
        const uint32_t sAl = sb + TILE_E * 2;
        const uint32_t sBh = sb + 2 * TILE_E * 2;
        const uint32_t sBl = sb + 3 * TILE_E * 2;

#pragma unroll
        for (int ks = 0; ks < 2; ks++) {
            const int kc = ks * 16 + (sub >> 1) * 8;   // k element offset for ldmatrix
            uint32_t ah[2][4], al[2][4];
#pragma unroll
            for (int mf = 0; mf < 2; mf++) {
                const uint32_t off =
                    (uint32_t)((mb + mf * 16 + (sub & 1) * 8 + lr) * LDT + kc) * 2;
                ldmx4(ah[mf], sAh + off);
                ldmx4(al[mf], sAl + off);
            }
#pragma unroll
            for (int p = 0; p < 4; p++) {
                const uint32_t boff =
                    (uint32_t)((nb + p * 16 + (sub & 1) * 8 + lr) * LDT + kc) * 2;
                uint32_t bh[4], bl[4];
                ldmx4(bh, sBh + boff);
                ldmx4(bl, sBl + boff);
                // n-frag 2p: {r0,r2}; n-frag 2p+1: {r1,r3}
#pragma unroll
                for (int mf = 0; mf < 2; mf++) {
                    mma16816(acc[mf][2 * p],     ah[mf], bh[0], bh[2]);
                    mma16816(acc[mf][2 * p + 1], ah[mf], bh[1], bh[3]);
                    mma16816(acc[mf][2 * p],     ah[mf], bl[0], bl[2]);
                    mma16816(acc[mf][2 * p + 1], ah[mf], bl[1], bl[3]);
                    mma16816(acc[mf][2 * p],     al[mf], bh[0], bh[2]);
                    mma16816(acc[mf][2 * p + 1], al[mf], bh[1], bh[3]);
                }
            }
        }
        __syncthreads();
    }

    // Epilogue: acc fragment -> C (+bias)
    const int er = lane >> 2;            // row within 8
    const int ec = (lane & 3) * 2;       // col pair
#pragma unroll
    for (int mf = 0; mf < 2; mf++) {
#pragma unroll
        for (int nf = 0; nf < 8; nf++) {
            const int row = m0 + mb + mf * 16 + er;
            const int col = n0 + nb + nf * 8 + ec;
            float b0 = bias ? bias[col]     : 0.f;
            float b1 = bias ? bias[col + 1] : 0.f;
            float2 v0 = make_float2(acc[mf][nf][0] + b0, acc[mf][nf][1] + b1);
            float2 v1 = make_float2(acc[mf][nf][2] + b0, acc[mf][nf][3] + b1);
            *(float2*)(C + (size_t)row * Nd + col)       = v0;
            *(float2*)(C + (size_t)(row + 8) * Nd + col) = v1;
        }
    }
}

// ---------------------------------------------------------------------------
// fp32 -> bf16 hi/lo split (elementwise, vectorized)
// ---------------------------------------------------------------------------
__global__ void __launch_bounds__(256) split_kernel(
    const float4* __restrict__ a, __nv_bfloat16* __restrict__ hi,
    __nv_bfloat16* __restrict__ lo, int n4)
{
    int i = blockIdx.x * blockDim.x + threadIdx.x;
    if (i >= n4) return;
    float4 v = a[i];
    float vv[4] = {v.x, v.y, v.z, v.w};
    __nv_bfloat16 h[4], l[4];
#pragma unroll
    for (int j = 0; j < 4; j++) {
        h[j] = __float2bfloat16(vv[j]);
        l[j] = __float2bfloat16(vv[j] - __bfloat162float(h[j]));
    }
    __nv_bfloat162 h01, h23, l01, l23;
    h01.x = h[0]; h01.y = h[1]; h23.x = h[2]; h23.y = h[3];
    l01.x = l[0]; l01.y = l[1]; l23.x = l[2]; l23.y = l[3];
    ((__nv_bfloat162*)hi)[i * 2]     = h01;
    ((__nv_bfloat162*)hi)[i * 2 + 1] = h23;
    ((__nv_bfloat162*)lo)[i * 2]     = l01;
    ((__nv_bfloat162*)lo)[i * 2 + 1] = l23;
}

// ---------------------------------------------------------------------------
// Weight transpose + split: W[K][N] -> T{h,l}[n][k] = split(W[k][n])
// ---------------------------------------------------------------------------
__global__ void __launch_bounds__(256) tsplit_kernel(
    const float* __restrict__ W, __nv_bfloat16* __restrict__ Th,
    __nv_bfloat16* __restrict__ Tl)
{
    __shared__ float s[32][33];
    const int n0 = blockIdx.x * 32;
    const int k0 = blockIdx.y * 32;
    const int tx = threadIdx.x, ty = threadIdx.y;  // 32 x 8
#pragma unroll
    for (int r = 0; r < 32; r += 8)
        s[ty + r][tx] = W[(size_t)(k0 + ty + r) * cD + n0 + tx];
    __syncthreads();
#pragma unroll
    for (int r = 0; r < 32; r += 8) {
        float v = s[tx][ty + r];  // = W[k0+tx][n0+ty+r]
        __nv_bfloat16 h = __float2bfloat16(v);
        __nv_bfloat16 l = __float2bfloat16(v - __bfloat162float(h));
        size_t o = (size_t)(n0 + ty + r) * cD + k0 + tx;
        Th[o] = h; Tl[o] = l;
    }
}

// ---------------------------------------------------------------------------
// Causal flash attention, fp32 (unchanged known-good version)
// ---------------------------------------------------------------------------
__global__ void __launch_bounds__(128) attn_kernel(
    const float* __restrict__ Q, const float* __restrict__ K,
    const float* __restrict__ V, float* __restrict__ ctx)
{
    constexpr int Br = 128, Bc = 32;
    const int qt = blockIdx.x;
    const int h  = blockIdx.y;
    const int b  = blockIdx.z;
    const int row = qt * Br + threadIdx.x;

    const float* qp = Q + ((size_t)(b * cS + row) * cD + h * cHD);
    float q[cHD];
#pragma unroll
    for (int d = 0; d < cHD; d += 4) {
        float4 t = *(const float4*)(qp + d);
        q[d]     = t.x * 0.125f;
        q[d + 1] = t.y * 0.125f;
        q[d + 2] = t.z * 0.125f;
        q[d + 3] = t.w * 0.125f;
    }

    float m = -INFINITY, l = 0.f;
    float acc[cHD];
#pragma unroll
    for (int d = 0; d < cHD; d++) acc[d] = 0.f;

    __shared__ float Ks[Bc][cHD];
    __shared__ float Vs[Bc][cHD];

    const int ntiles = qt * 4 + 4;
    const int lr = threadIdx.x >> 2;
    const int lc = (threadIdx.x & 3) << 4;

    for (int t = 0; t < ntiles; t++) {
        const int k0 = t * Bc;
        const float* kp = K + ((size_t)(b * cS + k0 + lr) * cD + h * cHD + lc);
        const float* vp = V + ((size_t)(b * cS + k0 + lr) * cD + h * cHD + lc);
#pragma unroll
        for (int i = 0; i < 16; i += 4) {
            *(float4*)&Ks[lr][lc + i] = *(const float4*)(kp + i);
            *(float4*)&Vs[lr][lc + i] = *(const float4*)(vp + i);
        }
        __syncthreads();

        float sc[Bc];
        float mt = m;
        const bool full = (k0 + Bc - 1 <= row);
#pragma unroll 8
        for (int j = 0; j < Bc; j++) {
            float s0 = 0.f, s1 = 0.f;
#pragma unroll
            for (int d = 0; d < cHD; d += 8) {
                float4 ka = *(const float4*)&Ks[j][d];
                float4 kb = *(const float4*)&Ks[j][d + 4];
                s0 = fmaf(q[d],     ka.x, s0);
                s0 = fmaf(q[d + 1], ka.y, s0);
                s0 = fmaf(q[d + 2], ka.z, s0);
                s0 = fmaf(q[d + 3], ka.w, s0);
                s1 = fmaf(q[d + 4], kb.x, s1);
                s1 = fmaf(q[d + 5], kb.y, s1);
                s1 = fmaf(q[d + 6], kb.z, s1);
                s1 = fmaf(q[d + 7], kb.w, s1);
            }
            float s = s0 + s1;
            if (!full && (k0 + j > row)) s = -INFINITY;
            sc[j] = s;
            mt = fmaxf(mt, s);
        }

        const float corr = __expf(m - mt);
        l *= corr;
#pragma unroll
        for (int d = 0; d < cHD; d++) acc[d] *= corr;

#pragma unroll 8
        for (int j = 0; j < Bc; j++) {
            const float p = __expf(sc[j] - mt);
            l += p;
#pragma unroll
            for (int d = 0; d < cHD; d += 4) {
                float4 v4 = *(const float4*)&Vs[j][d];
                acc[d]     = fmaf(p, v4.x, acc[d]);
                acc[d + 1] = fmaf(p, v4.y, acc[d + 1]);
                acc[d + 2] = fmaf(p, v4.z, acc[d + 2]);
                acc[d + 3] = fmaf(p, v4.w, acc[d + 3]);
            }
        }
        m = mt;
        __syncthreads();
    }

    const float inv = 1.f / l;
    float* op = ctx + ((size_t)(b * cS + row) * cD + h * cHD);
#pragma unroll
    for (int d = 0; d < cHD; d += 4) {
        float4 o = make_float4(acc[d] * inv, acc[d + 1] * inv,
                               acc[d + 2] * inv, acc[d + 3] * inv);
        *(float4*)(op + d) = o;
    }
}

// ---------------------------------------------------------------------------
// Launch
// ---------------------------------------------------------------------------
extern "C" void kernel_launch(void* const* d_in, const int* /*in_sizes*/, int /*n_in*/,
                              void* d_out, int /*out_size*/)
{
    const float* x  = (const float*)d_in[0];
    const float* Wq = (const float*)d_in[1];
    const float* Wk = (const float*)d_in[2];
    const float* Wv = (const float*)d_in[3];
    const float* Wo = (const float*)d_in[4];
    const float* bo = (const float*)d_in[5];
    float* out = (float*)d_out;

    float *Qp, *Kp, *Vp, *Cp;
    __nv_bfloat16 *xh, *xl, *ch, *cl;
    __nv_bfloat16 *wqh, *wql, *wkh, *wkl, *wvh, *wvl, *woh, *wol;
    cudaGetSymbolAddress((void**)&Qp, g_Q);
    cudaGetSymbolAddress((void**)&Kp, g_K);
    cudaGetSymbolAddress((void**)&Vp, g_V);
    cudaGetSymbolAddress((void**)&Cp, g_ctx);
    cudaGetSymbolAddress((void**)&xh, g_xh);
    cudaGetSymbolAddress((void**)&xl, g_xl);
    cudaGetSymbolAddress((void**)&ch, g_ch);
    cudaGetSymbolAddress((void**)&cl, g_cl);
    cudaGetSymbolAddress((void**)&wqh, g_Wqh);
    cudaGetSymbolAddress((void**)&wql, g_Wql);
    cudaGetSymbolAddress((void**)&wkh, g_Wkh);
    cudaGetSymbolAddress((void**)&wkl, g_Wkl);
    cudaGetSymbolAddress((void**)&wvh, g_Wvh);
    cudaGetSymbolAddress((void**)&wvl, g_Wvl);
    cudaGetSymbolAddress((void**)&woh, g_Woh);
    cudaGetSymbolAddress((void**)&wol, g_Wol);

    cudaFuncSetAttribute(gemm_bf16x3_kernel,
                         cudaFuncAttributeMaxDynamicSharedMemorySize, GEMM_SMEM);

    const int n4 = cM * cD / 4;
    split_kernel<<<(n4 + 255) / 256, 256>>>((const float4*)x, xh, xl, n4);

    dim3 tg(cD / 32, cD / 32), tb(32, 8);
    tsplit_kernel<<<tg, tb>>>(Wq, wqh, wql);
    tsplit_kernel<<<tg, tb>>>(Wk, wkh, wkl);
    tsplit_kernel<<<tg, tb>>>(Wv, wvh, wvl);
    tsplit_kernel<<<tg, tb>>>(Wo, woh, wol);

    dim3 gg(cD / 128, cM / 128);  // (8, 32)
    gemm_bf16x3_kernel<<<gg, 256, GEMM_SMEM>>>(xh, xl, wqh, wql, nullptr, Qp, cD, cD);
    gemm_bf16x3_kernel<<<gg, 256, GEMM_SMEM>>>(xh, xl, wkh, wkl, nullptr, Kp, cD, cD);
    gemm_bf16x3_kernel<<<gg, 256, GEMM_SMEM>>>(xh, xl, wvh, wvl, nullptr, Vp, cD, cD);

    dim3 ga(cS / 128, cH, cB);    // (16, 16, 2)
    attn_kernel<<<ga, 128>>>(Qp, Kp, Vp, Cp);

    split_kernel<<<(n4 + 255) / 256, 256>>>((const float4*)Cp, ch, cl, n4);
    gemm_bf16x3_kernel<<<gg, 256, GEMM_SMEM>>>(ch, cl, woh, wol, bo, out, cD, cD);
}